// round 12
// baseline (speedup 1.0000x reference)
#include <cuda_runtime.h>
#include <cuda_fp16.h>
#include <math.h>

#define B_TOT 32768
#define F_TOT 512
#define H_TOT 10
#define H_F16 9              // h 0..8 on f16x2 MUFU path; h 9 on FMA-pipe poly

#define THREADS 512
#define NWARP (THREADS / 32)
#define CHUNK 32
#define NB 4

#define PCLAMP 3.8f
#define PC2 (PCLAMP * PCLAMP)
#define NCOEF 10             // degree-9 poly in v = z^2  (odd degree 19 in z)

__device__ float    g_poly[NCOEF];
__constant__ float  c_poly[NCOEF];

__device__ __forceinline__ __half2 tanh2_fast(__half2 v) {
    unsigned a = *reinterpret_cast<unsigned*>(&v), r;
    asm("tanh.approx.f16x2 %0, %1;" : "=r"(r) : "r"(a));
    return *reinterpret_cast<__half2*>(&r);
}

__device__ __forceinline__ float warp_sum(float v) {
#pragma unroll
    for (int off = 16; off > 0; off >>= 1)
        v += __shfl_xor_sync(0xFFFFFFFFu, v, off);
    return v;
}

// ---------------------------------------------------------------------------
// Fit kernel: Q(s) = tanh(C*sqrt(s))/(C*sqrt(s)) on s in [0,1], degree 9.
// Chebyshev interpolation at 10 nodes -> coeffs c_k; convert to monomial in s
// via shifted-Chebyshev recurrence (integer coeffs, exact in fp32, max 589824
// < 2^24); rescale to v = z^2. Runs once, ~0.5us, threads redundant.
// ---------------------------------------------------------------------------
__global__ void fit_kernel() {
    const float PI = 3.14159265358979f;
    float fj[NCOEF], cb[NCOEF];
#pragma unroll
    for (int j = 0; j < NCOEF; j++) {
        float u = __cosf(PI * (j + 0.5f) / NCOEF);
        float s = 0.5f * (1.0f + u);
        float z = PCLAMP * sqrtf(s);
        fj[j] = tanhf(z) / z;              // z >= 0.27 at all nodes: safe
    }
#pragma unroll
    for (int k = 0; k < NCOEF; k++) {
        float sum = 0.0f;
#pragma unroll
        for (int j = 0; j < NCOEF; j++)
            sum += fj[j] * __cosf(PI * k * (j + 0.5f) / NCOEF);
        cb[k] = (2.0f / NCOEF) * sum;
    }
    cb[0] *= 0.5f;

    // monomial accumulation: b[i] = sum_k cb[k] * Tstar_k[i]
    float b[NCOEF], tm1[NCOEF], tk[NCOEF], tn[NCOEF];
#pragma unroll
    for (int i = 0; i < NCOEF; i++) { b[i] = 0.f; tm1[i] = 0.f; tk[i] = 0.f; }
    tm1[0] = 1.0f;                       // T*_0 = 1
    b[0] += cb[0];
    tk[0] = -1.0f; tk[1] = 2.0f;         // T*_1 = 2s - 1
#pragma unroll
    for (int i = 0; i < NCOEF; i++) b[i] += cb[1] * tk[i];
#pragma unroll
    for (int k = 2; k < NCOEF; k++) {
        // T*_{k} = (4s - 2) T*_{k-1} - T*_{k-2}
#pragma unroll
        for (int i = 0; i < NCOEF; i++) {
            float sh = (i > 0) ? tk[i - 1] : 0.0f;
            tn[i] = 4.0f * sh - 2.0f * tk[i] - tm1[i];
        }
#pragma unroll
        for (int i = 0; i < NCOEF; i++) {
            b[i] += cb[k] * tn[i];
            tm1[i] = tk[i]; tk[i] = tn[i];
        }
    }
    // rescale s = v / C^2  ->  coeff_i /= C^(2i)
    if (threadIdx.x == 0) {
        float scale = 1.0f;
#pragma unroll
        for (int i = 0; i < NCOEF; i++) { g_poly[i] = b[i] * scale; scale /= PC2; }
    }
}

// ---------------------------------------------------------------------------
// Main kernel: R6 scaffold. h=0..8 via f16x2 tanh2 (MUFU); h=9 via fp32
// clamped odd polynomial on the FMA pipe (coeffs in __constant__ -> UR regs).
// ---------------------------------------------------------------------------
__global__ __launch_bounds__(THREADS, 2)
void neural_unilasso_kernel(const float* __restrict__ x,
                            const float* __restrict__ W1,
                            const float* __restrict__ b1,
                            const float* __restrict__ W2,
                            const float* __restrict__ b2,
                            const float* __restrict__ theta,
                            const float* __restrict__ bias,
                            float* __restrict__ y,
                            float* __restrict__ y_theta) {
    __shared__ float part[CHUNK * 17];
    __shared__ float s_red[NWARP];
    __shared__ float s_base;

    const int tid  = threadIdx.x;
    const int lane = tid & 31;
    const int warp = tid >> 5;
    const int f    = warp * 32 + lane;

    const float th = theta[f];
    const float st = log1pf(expf(th));
    if (blockIdx.x == 0) y_theta[f] = st;

    __half2 w1h[H_F16], b1h[H_F16];
    float w2r[H_F16];
#pragma unroll
    for (int h = 0; h < H_F16; h++) {
        float w1 = __ldg(&W1[f * H_TOT + h]);
        float bb = __ldg(&b1[f * H_TOT + h]);
        w1h[h] = __floats2half2_rn(w1, w1);
        b1h[h] = __floats2half2_rn(bb, bb);
        w2r[h] = __ldg(&W2[f * H_TOT + h]) * st;
    }
    const float w1p = __ldg(&W1[f * H_TOT + H_F16]);
    const float b1p = __ldg(&b1[f * H_TOT + H_F16]);
    const float w2p = __ldg(&W2[f * H_TOT + H_F16]) * st;
    {
        float c = warp_sum(b2[f] * st);
        if (lane == 0) s_red[warp] = c;
        __syncthreads();
        if (tid == 0) {
            float s = bias[0];
#pragma unroll
            for (int w = 0; w < NWARP; w++) s += s_red[w];
            s_base = s;
        }
        __syncthreads();
    }

    const int bchunk = blockIdx.x * CHUNK;
    const float* xp = x + (size_t)bchunk * F_TOT + f;

    float xc0 = __ldg(xp + 0 * F_TOT);
    float xc1 = __ldg(xp + 1 * F_TOT);
    float xc2 = __ldg(xp + 2 * F_TOT);
    float xc3 = __ldg(xp + 3 * F_TOT);

#pragma unroll 1
    for (int g = 0; g < CHUNK; g += NB) {
        float xn0, xn1, xn2, xn3;
        if (g + NB < CHUNK) {
            xn0 = __ldg(xp + (size_t)(g + NB + 0) * F_TOT);
            xn1 = __ldg(xp + (size_t)(g + NB + 1) * F_TOT);
            xn2 = __ldg(xp + (size_t)(g + NB + 2) * F_TOT);
            xn3 = __ldg(xp + (size_t)(g + NB + 3) * F_TOT);
        }

        float a0 = 0.f, a1 = 0.f, a2 = 0.f, a3 = 0.f;

        // ---- poly path, h = 9 (FMA pipe; no MUFU) ----
        {
            float z0 = fmaf(xc0, w1p, b1p);
            float z1 = fmaf(xc1, w1p, b1p);
            float z2 = fmaf(xc2, w1p, b1p);
            float z3 = fmaf(xc3, w1p, b1p);
            z0 = fminf(fmaxf(z0, -PCLAMP), PCLAMP);
            z1 = fminf(fmaxf(z1, -PCLAMP), PCLAMP);
            z2 = fminf(fmaxf(z2, -PCLAMP), PCLAMP);
            z3 = fminf(fmaxf(z3, -PCLAMP), PCLAMP);
            float v0 = z0 * z0, v1 = z1 * z1, v2 = z2 * z2, v3 = z3 * z3;
            float q0 = c_poly[NCOEF - 1];
            float q1 = q0, q2 = q0, q3 = q0;
#pragma unroll
            for (int i = NCOEF - 2; i >= 0; i--) {
                q0 = fmaf(q0, v0, c_poly[i]);
                q1 = fmaf(q1, v1, c_poly[i]);
                q2 = fmaf(q2, v2, c_poly[i]);
                q3 = fmaf(q3, v3, c_poly[i]);
            }
            a0 = fmaf(z0 * q0, w2p, a0);
            a1 = fmaf(z1 * q1, w2p, a1);
            a2 = fmaf(z2 * q2, w2p, a2);
            a3 = fmaf(z3 * q3, w2p, a3);
        }

        // ---- f16x2 MUFU path, h = 0..8 ----
        const __half2 x01 = __floats2half2_rn(xc0, xc1);
        const __half2 x23 = __floats2half2_rn(xc2, xc3);
#pragma unroll
        for (int h = 0; h < H_F16; h++) {
            __half2 p01 = __hfma2(x01, w1h[h], b1h[h]);
            __half2 p23 = __hfma2(x23, w1h[h], b1h[h]);
            __half2 t01 = tanh2_fast(p01);
            __half2 t23 = tanh2_fast(p23);
            float2 f01 = __half22float2(t01);
            float2 f23 = __half22float2(t23);
            a0 = fmaf(f01.x, w2r[h], a0);
            a1 = fmaf(f01.y, w2r[h], a1);
            a2 = fmaf(f23.x, w2r[h], a2);
            a3 = fmaf(f23.y, w2r[h], a3);
        }

        // folded 4-accumulator warp reduction (11 SHFL)
        a0 += __shfl_xor_sync(0xFFFFFFFFu, a0, 16);
        a1 += __shfl_xor_sync(0xFFFFFFFFu, a1, 16);
        a2 += __shfl_xor_sync(0xFFFFFFFFu, a2, 16);
        a3 += __shfl_xor_sync(0xFFFFFFFFu, a3, 16);
        a0 += __shfl_xor_sync(0xFFFFFFFFu, a0, 8);
        a1 += __shfl_xor_sync(0xFFFFFFFFu, a1, 8);
        a2 += __shfl_xor_sync(0xFFFFFFFFu, a2, 8);
        a3 += __shfl_xor_sync(0xFFFFFFFFu, a3, 8);
        int q = (lane >> 3) & 3;
        float c = (q == 0) ? a0 : (q == 1) ? a1 : (q == 2) ? a2 : a3;
        c += __shfl_xor_sync(0xFFFFFFFFu, c, 4);
        c += __shfl_xor_sync(0xFFFFFFFFu, c, 2);
        c += __shfl_xor_sync(0xFFFFFFFFu, c, 1);
        if ((lane & 7) == 0)
            part[(g + q) * 17 + warp] = c;

        xc0 = xn0; xc1 = xn1; xc2 = xn2; xc3 = xn3;
    }
    __syncthreads();

    if (tid < CHUNK) {
        float s = s_base;
#pragma unroll
        for (int w = 0; w < NWARP; w++) s += part[tid * 17 + w];
        y[bchunk + tid] = s;
    }
}

// ---------------------------------------------------------------------------
// kernel_launch: inputs in setup_inputs order:
//   0:x  1:W1  2:b1  3:W2  4:b2  5:theta  6:bias ; out = y_pred(B) ++ nn_theta(F)
// ---------------------------------------------------------------------------
extern "C" void kernel_launch(void* const* d_in, const int* in_sizes, int n_in,
                              void* d_out, int out_size) {
    const float* x     = (const float*)d_in[0];
    const float* W1    = (const float*)d_in[1];
    const float* b1    = (const float*)d_in[2];
    const float* W2    = (const float*)d_in[3];
    const float* b2    = (const float*)d_in[4];
    const float* theta = (const float*)d_in[5];
    const float* bias  = (const float*)d_in[6];
    float* out = (float*)d_out;

    fit_kernel<<<1, 32>>>();
    void* gp = nullptr;
    cudaGetSymbolAddress(&gp, g_poly);
    cudaMemcpyToSymbolAsync(c_poly, gp, sizeof(float) * NCOEF, 0,
                            cudaMemcpyDeviceToDevice, 0);
    neural_unilasso_kernel<<<B_TOT / CHUNK, THREADS>>>(
        x, W1, b1, W2, b2, theta, bias, out, out + B_TOT);
}

// round 13
// speedup vs baseline: 1.0448x; 1.0448x over previous
#include <cuda_runtime.h>
#include <cuda_fp16.h>
#include <math.h>

#define B_TOT 32768
#define F_TOT 512
#define H_TOT 10

#define THREADS 512          // 16 warps; warp w covers features [32w, 32w+32)
#define NWARP (THREADS / 32)
#define CHUNK 16             // batches per block (halved vs R6: finer tail granularity)
#define NB 4                 // batches per inner group (2 half2 pairs)

__device__ __forceinline__ __half2 tanh2_fast(__half2 v) {
    unsigned a = *reinterpret_cast<unsigned*>(&v), r;
    asm("tanh.approx.f16x2 %0, %1;" : "=r"(r) : "r"(a));
    return *reinterpret_cast<__half2*>(&r);
}

__device__ __forceinline__ float warp_sum(float v) {
#pragma unroll
    for (int off = 16; off > 0; off >>= 1)
        v += __shfl_xor_sync(0xFFFFFFFFu, v, off);
    return v;
}

// ---------------------------------------------------------------------------
// R6 core (best measured: 50.8us), rescheduled with CHUNK=16 / grid=2048 to
// shrink last-wave tail granularity. Lane owns one feature; params in regs
// (W1/b1 broadcast half2, w2*softplus fp32). Inner loop per h: 2 HFMA2 arg +
// 2 tanh2 (MUFU) + 2 cvt-pair + 4 fp32 FFMA acc.
// ---------------------------------------------------------------------------
__global__ __launch_bounds__(THREADS, 2)
void neural_unilasso_kernel(const float* __restrict__ x,
                            const float* __restrict__ W1,
                            const float* __restrict__ b1,
                            const float* __restrict__ W2,
                            const float* __restrict__ b2,
                            const float* __restrict__ theta,
                            const float* __restrict__ bias,
                            float* __restrict__ y,
                            float* __restrict__ y_theta) {
    __shared__ float part[CHUNK * 17];   // [batch][warp], padded stride
    __shared__ float s_red[NWARP];
    __shared__ float s_base;

    const int tid  = threadIdx.x;
    const int lane = tid & 31;
    const int warp = tid >> 5;
    const int f    = warp * 32 + lane;   // THREADS == F_TOT

    // ---- prologue: params + softplus + csum ----
    const float th = theta[f];
    const float st = log1pf(expf(th));           // softplus
    if (blockIdx.x == 0) y_theta[f] = st;        // nn_theta output

    __half2 w1h[H_TOT], b1h[H_TOT];
    float w2r[H_TOT];
#pragma unroll
    for (int h = 0; h < H_TOT; h++) {
        float w1 = __ldg(&W1[f * H_TOT + h]);
        float bb = __ldg(&b1[f * H_TOT + h]);
        w1h[h] = __floats2half2_rn(w1, w1);
        b1h[h] = __floats2half2_rn(bb, bb);
        w2r[h] = __ldg(&W2[f * H_TOT + h]) * st; // fp32, exact scaling
    }
    {
        float c = warp_sum(b2[f] * st);
        if (lane == 0) s_red[warp] = c;
        __syncthreads();
        if (tid == 0) {
            float s = bias[0];
#pragma unroll
            for (int w = 0; w < NWARP; w++) s += s_red[w];
            s_base = s;
        }
        __syncthreads();
    }

    const int bchunk = blockIdx.x * CHUNK;
    const float* xp = x + (size_t)bchunk * F_TOT + f;

    // depth-1 prefetch
    float xc0 = __ldg(xp + 0 * F_TOT);
    float xc1 = __ldg(xp + 1 * F_TOT);
    float xc2 = __ldg(xp + 2 * F_TOT);
    float xc3 = __ldg(xp + 3 * F_TOT);

#pragma unroll 1
    for (int g = 0; g < CHUNK; g += NB) {
        float xn0, xn1, xn2, xn3;
        if (g + NB < CHUNK) {
            xn0 = __ldg(xp + (size_t)(g + NB + 0) * F_TOT);
            xn1 = __ldg(xp + (size_t)(g + NB + 1) * F_TOT);
            xn2 = __ldg(xp + (size_t)(g + NB + 2) * F_TOT);
            xn3 = __ldg(xp + (size_t)(g + NB + 3) * F_TOT);
        }

        const __half2 x01 = __floats2half2_rn(xc0, xc1);
        const __half2 x23 = __floats2half2_rn(xc2, xc3);

        float a0 = 0.f, a1 = 0.f, a2 = 0.f, a3 = 0.f;
#pragma unroll
        for (int h = 0; h < H_TOT; h++) {
            __half2 p01 = __hfma2(x01, w1h[h], b1h[h]);
            __half2 p23 = __hfma2(x23, w1h[h], b1h[h]);
            __half2 t01 = tanh2_fast(p01);
            __half2 t23 = tanh2_fast(p23);
            float2 f01 = __half22float2(t01);
            float2 f23 = __half22float2(t23);
            a0 = fmaf(f01.x, w2r[h], a0);
            a1 = fmaf(f01.y, w2r[h], a1);
            a2 = fmaf(f23.x, w2r[h], a2);
            a3 = fmaf(f23.y, w2r[h], a3);
        }

        // folded 4-accumulator warp reduction (11 SHFL)
        a0 += __shfl_xor_sync(0xFFFFFFFFu, a0, 16);
        a1 += __shfl_xor_sync(0xFFFFFFFFu, a1, 16);
        a2 += __shfl_xor_sync(0xFFFFFFFFu, a2, 16);
        a3 += __shfl_xor_sync(0xFFFFFFFFu, a3, 16);
        a0 += __shfl_xor_sync(0xFFFFFFFFu, a0, 8);
        a1 += __shfl_xor_sync(0xFFFFFFFFu, a1, 8);
        a2 += __shfl_xor_sync(0xFFFFFFFFu, a2, 8);
        a3 += __shfl_xor_sync(0xFFFFFFFFu, a3, 8);
        int q = (lane >> 3) & 3;
        float c = (q == 0) ? a0 : (q == 1) ? a1 : (q == 2) ? a2 : a3;
        c += __shfl_xor_sync(0xFFFFFFFFu, c, 4);
        c += __shfl_xor_sync(0xFFFFFFFFu, c, 2);
        c += __shfl_xor_sync(0xFFFFFFFFu, c, 1);
        if ((lane & 7) == 0)
            part[(g + q) * 17 + warp] = c;

        xc0 = xn0; xc1 = xn1; xc2 = xn2; xc3 = xn3;
    }
    __syncthreads();

    if (tid < CHUNK) {
        float s = s_base;
#pragma unroll
        for (int w = 0; w < NWARP; w++) s += part[tid * 17 + w];
        y[bchunk + tid] = s;
    }
}

// ---------------------------------------------------------------------------
// kernel_launch: inputs in setup_inputs order:
//   0:x (B,F)  1:W1 (F,H)  2:b1 (F,H)  3:W2 (F,H)  4:b2 (F)  5:theta (F)  6:bias (1)
// output: y_pred (B) then nn_theta (F), fp32.
// ---------------------------------------------------------------------------
extern "C" void kernel_launch(void* const* d_in, const int* in_sizes, int n_in,
                              void* d_out, int out_size) {
    const float* x     = (const float*)d_in[0];
    const float* W1    = (const float*)d_in[1];
    const float* b1    = (const float*)d_in[2];
    const float* W2    = (const float*)d_in[3];
    const float* b2    = (const float*)d_in[4];
    const float* theta = (const float*)d_in[5];
    const float* bias  = (const float*)d_in[6];
    float* out = (float*)d_out;

    neural_unilasso_kernel<<<B_TOT / CHUNK, THREADS>>>(
        x, W1, b1, W2, b2, theta, bias, out, out + B_TOT);
}

// round 14
// speedup vs baseline: 1.0481x; 1.0031x over previous
#include <cuda_runtime.h>
#include <cuda_fp16.h>
#include <math.h>

#define B_TOT 32768
#define F_TOT 512
#define H_TOT 10

#define THREADS 512          // 16 warps; warp w covers features [32w, 32w+32)
#define NWARP (THREADS / 32)
#define CHUNK 32             // batches per block (R6-proven schedule)
#define NB 8                 // batches per inner group (4 half2 pairs)

__device__ __forceinline__ __half2 tanh2_fast(__half2 v) {
    unsigned a = *reinterpret_cast<unsigned*>(&v), r;
    asm("tanh.approx.f16x2 %0, %1;" : "=r"(r) : "r"(a));
    return *reinterpret_cast<__half2*>(&r);
}

__device__ __forceinline__ float warp_sum(float v) {
#pragma unroll
    for (int off = 16; off > 0; off >>= 1)
        v += __shfl_xor_sync(0xFFFFFFFFu, v, off);
    return v;
}

// ---------------------------------------------------------------------------
// R6 core with NB=8: 4 outer iterations per chunk (halved loop overhead),
// 8 front-batched LDGs per group (MLP=8). Numerics identical to R6:
// HFMA2 arg + tanh2 (MUFU) + fp32 accumulation with fp32 w2*softplus.
// ---------------------------------------------------------------------------
__global__ __launch_bounds__(THREADS, 2)
void neural_unilasso_kernel(const float* __restrict__ x,
                            const float* __restrict__ W1,
                            const float* __restrict__ b1,
                            const float* __restrict__ W2,
                            const float* __restrict__ b2,
                            const float* __restrict__ theta,
                            const float* __restrict__ bias,
                            float* __restrict__ y,
                            float* __restrict__ y_theta) {
    __shared__ float part[CHUNK * 17];   // [batch][warp], padded stride
    __shared__ float s_red[NWARP];
    __shared__ float s_base;

    const int tid  = threadIdx.x;
    const int lane = tid & 31;
    const int warp = tid >> 5;
    const int f    = warp * 32 + lane;   // THREADS == F_TOT

    // ---- prologue: params + softplus + csum ----
    const float th = theta[f];
    const float st = log1pf(expf(th));           // softplus
    if (blockIdx.x == 0) y_theta[f] = st;        // nn_theta output

    __half2 w1h[H_TOT], b1h[H_TOT];
    float w2r[H_TOT];
#pragma unroll
    for (int h = 0; h < H_TOT; h++) {
        float w1 = __ldg(&W1[f * H_TOT + h]);
        float bb = __ldg(&b1[f * H_TOT + h]);
        w1h[h] = __floats2half2_rn(w1, w1);
        b1h[h] = __floats2half2_rn(bb, bb);
        w2r[h] = __ldg(&W2[f * H_TOT + h]) * st; // fp32, exact scaling
    }
    {
        float c = warp_sum(b2[f] * st);
        if (lane == 0) s_red[warp] = c;
        __syncthreads();
        if (tid == 0) {
            float s = bias[0];
#pragma unroll
            for (int w = 0; w < NWARP; w++) s += s_red[w];
            s_base = s;
        }
        __syncthreads();
    }

    const int bchunk = blockIdx.x * CHUNK;
    const float* xp = x + (size_t)bchunk * F_TOT + f;

#pragma unroll 1
    for (int g = 0; g < CHUNK; g += NB) {
        // front-batched loads: 8 independent LDGs in flight (MLP=8)
        float x0 = __ldg(xp + (size_t)(g + 0) * F_TOT);
        float x1 = __ldg(xp + (size_t)(g + 1) * F_TOT);
        float x2 = __ldg(xp + (size_t)(g + 2) * F_TOT);
        float x3 = __ldg(xp + (size_t)(g + 3) * F_TOT);
        float x4 = __ldg(xp + (size_t)(g + 4) * F_TOT);
        float x5 = __ldg(xp + (size_t)(g + 5) * F_TOT);
        float x6 = __ldg(xp + (size_t)(g + 6) * F_TOT);
        float x7 = __ldg(xp + (size_t)(g + 7) * F_TOT);

        const __half2 x01 = __floats2half2_rn(x0, x1);
        const __half2 x23 = __floats2half2_rn(x2, x3);
        const __half2 x45 = __floats2half2_rn(x4, x5);
        const __half2 x67 = __floats2half2_rn(x6, x7);

        float a0 = 0.f, a1 = 0.f, a2 = 0.f, a3 = 0.f;
        float a4 = 0.f, a5 = 0.f, a6 = 0.f, a7 = 0.f;
#pragma unroll
        for (int h = 0; h < H_TOT; h++) {
            __half2 p01 = __hfma2(x01, w1h[h], b1h[h]);
            __half2 p23 = __hfma2(x23, w1h[h], b1h[h]);
            __half2 p45 = __hfma2(x45, w1h[h], b1h[h]);
            __half2 p67 = __hfma2(x67, w1h[h], b1h[h]);
            __half2 t01 = tanh2_fast(p01);
            __half2 t23 = tanh2_fast(p23);
            __half2 t45 = tanh2_fast(p45);
            __half2 t67 = tanh2_fast(p67);
            float2 f01 = __half22float2(t01);
            float2 f23 = __half22float2(t23);
            float2 f45 = __half22float2(t45);
            float2 f67 = __half22float2(t67);
            a0 = fmaf(f01.x, w2r[h], a0);
            a1 = fmaf(f01.y, w2r[h], a1);
            a2 = fmaf(f23.x, w2r[h], a2);
            a3 = fmaf(f23.y, w2r[h], a3);
            a4 = fmaf(f45.x, w2r[h], a4);
            a5 = fmaf(f45.y, w2r[h], a5);
            a6 = fmaf(f67.x, w2r[h], a6);
            a7 = fmaf(f67.y, w2r[h], a7);
        }

        // two folded 4-accumulator warp reductions (11 SHFL each)
        a0 += __shfl_xor_sync(0xFFFFFFFFu, a0, 16);
        a1 += __shfl_xor_sync(0xFFFFFFFFu, a1, 16);
        a2 += __shfl_xor_sync(0xFFFFFFFFu, a2, 16);
        a3 += __shfl_xor_sync(0xFFFFFFFFu, a3, 16);
        a4 += __shfl_xor_sync(0xFFFFFFFFu, a4, 16);
        a5 += __shfl_xor_sync(0xFFFFFFFFu, a5, 16);
        a6 += __shfl_xor_sync(0xFFFFFFFFu, a6, 16);
        a7 += __shfl_xor_sync(0xFFFFFFFFu, a7, 16);
        a0 += __shfl_xor_sync(0xFFFFFFFFu, a0, 8);
        a1 += __shfl_xor_sync(0xFFFFFFFFu, a1, 8);
        a2 += __shfl_xor_sync(0xFFFFFFFFu, a2, 8);
        a3 += __shfl_xor_sync(0xFFFFFFFFu, a3, 8);
        a4 += __shfl_xor_sync(0xFFFFFFFFu, a4, 8);
        a5 += __shfl_xor_sync(0xFFFFFFFFu, a5, 8);
        a6 += __shfl_xor_sync(0xFFFFFFFFu, a6, 8);
        a7 += __shfl_xor_sync(0xFFFFFFFFu, a7, 8);
        int q = (lane >> 3) & 3;                 // quarter selects accumulator
        float cA = (q == 0) ? a0 : (q == 1) ? a1 : (q == 2) ? a2 : a3;
        float cB = (q == 0) ? a4 : (q == 1) ? a5 : (q == 2) ? a6 : a7;
        cA += __shfl_xor_sync(0xFFFFFFFFu, cA, 4);
        cB += __shfl_xor_sync(0xFFFFFFFFu, cB, 4);
        cA += __shfl_xor_sync(0xFFFFFFFFu, cA, 2);
        cB += __shfl_xor_sync(0xFFFFFFFFu, cB, 2);
        cA += __shfl_xor_sync(0xFFFFFFFFu, cA, 1);
        cB += __shfl_xor_sync(0xFFFFFFFFu, cB, 1);
        if ((lane & 7) == 0) {
            part[(g + q) * 17 + warp]     = cA;
            part[(g + 4 + q) * 17 + warp] = cB;
        }
    }
    __syncthreads();

    if (tid < CHUNK) {
        float s = s_base;
#pragma unroll
        for (int w = 0; w < NWARP; w++) s += part[tid * 17 + w];
        y[bchunk + tid] = s;
    }
}

// ---------------------------------------------------------------------------
// kernel_launch: inputs in setup_inputs order:
//   0:x (B,F)  1:W1 (F,H)  2:b1 (F,H)  3:W2 (F,H)  4:b2 (F)  5:theta (F)  6:bias (1)
// output: y_pred (B) then nn_theta (F), fp32.
// ---------------------------------------------------------------------------
extern "C" void kernel_launch(void* const* d_in, const int* in_sizes, int n_in,
                              void* d_out, int out_size) {
    const float* x     = (const float*)d_in[0];
    const float* W1    = (const float*)d_in[1];
    const float* b1    = (const float*)d_in[2];
    const float* W2    = (const float*)d_in[3];
    const float* b2    = (const float*)d_in[4];
    const float* theta = (const float*)d_in[5];
    const float* bias  = (const float*)d_in[6];
    float* out = (float*)d_out;

    neural_unilasso_kernel<<<B_TOT / CHUNK, THREADS>>>(
        x, W1, b1, W2, b2, theta, bias, out, out + B_TOT);
}

// round 15
// speedup vs baseline: 1.0917x; 1.0416x over previous
#include <cuda_runtime.h>
#include <cuda_fp16.h>
#include <math.h>

#define B_TOT 32768
#define F_TOT 512
#define H_TOT 10

#define THREADS 512          // 16 warps; warp w covers features [32w, 32w+32)
#define NWARP (THREADS / 32)
#define CHUNK 32             // batches per block
#define NB 4                 // batches per inner group (2 half2 pairs)

__device__ __forceinline__ __half2 tanh2_fast(__half2 v) {
    unsigned a = *reinterpret_cast<unsigned*>(&v), r;
    asm("tanh.approx.f16x2 %0, %1;" : "=r"(r) : "r"(a));
    return *reinterpret_cast<__half2*>(&r);
}

__device__ __forceinline__ float warp_sum(float v) {
#pragma unroll
    for (int off = 16; off > 0; off >>= 1)
        v += __shfl_xor_sync(0xFFFFFFFFu, v, off);
    return v;
}

// ---------------------------------------------------------------------------
// Converged optimum (R6, measured 50.8us @ 93% of the MUFU tanh floor).
// Lane owns one feature; all params in registers (W1/b1 broadcast half2,
// w2*softplus fp32). Inner loop per h: 2 HFMA2 arg + 2 tanh2 (MUFU) +
// 2 cvt-pair + 4 fp32 FFMA acc. Folded 11-SHFL reduction per 4-batch group.
// ---------------------------------------------------------------------------
__global__ __launch_bounds__(THREADS, 2)
void neural_unilasso_kernel(const float* __restrict__ x,
                            const float* __restrict__ W1,
                            const float* __restrict__ b1,
                            const float* __restrict__ W2,
                            const float* __restrict__ b2,
                            const float* __restrict__ theta,
                            const float* __restrict__ bias,
                            float* __restrict__ y,
                            float* __restrict__ y_theta) {
    __shared__ float part[CHUNK * 17];   // [batch][warp], padded stride
    __shared__ float s_red[NWARP];
    __shared__ float s_base;

    const int tid  = threadIdx.x;
    const int lane = tid & 31;
    const int warp = tid >> 5;
    const int f    = warp * 32 + lane;   // THREADS == F_TOT

    // ---- prologue: params + softplus + csum ----
    const float th = theta[f];
    const float st = log1pf(expf(th));           // softplus
    if (blockIdx.x == 0) y_theta[f] = st;        // nn_theta output

    __half2 w1h[H_TOT], b1h[H_TOT];
    float w2r[H_TOT];
#pragma unroll
    for (int h = 0; h < H_TOT; h++) {
        float w1 = __ldg(&W1[f * H_TOT + h]);
        float bb = __ldg(&b1[f * H_TOT + h]);
        w1h[h] = __floats2half2_rn(w1, w1);
        b1h[h] = __floats2half2_rn(bb, bb);
        w2r[h] = __ldg(&W2[f * H_TOT + h]) * st; // fp32, exact scaling
    }
    {
        float c = warp_sum(b2[f] * st);
        if (lane == 0) s_red[warp] = c;
        __syncthreads();
        if (tid == 0) {
            float s = bias[0];
#pragma unroll
            for (int w = 0; w < NWARP; w++) s += s_red[w];
            s_base = s;
        }
        __syncthreads();
    }

    const int bchunk = blockIdx.x * CHUNK;
    const float* xp = x + (size_t)bchunk * F_TOT + f;

    // depth-1 prefetch
    float xc0 = __ldg(xp + 0 * F_TOT);
    float xc1 = __ldg(xp + 1 * F_TOT);
    float xc2 = __ldg(xp + 2 * F_TOT);
    float xc3 = __ldg(xp + 3 * F_TOT);

#pragma unroll 1
    for (int g = 0; g < CHUNK; g += NB) {
        float xn0, xn1, xn2, xn3;
        if (g + NB < CHUNK) {
            xn0 = __ldg(xp + (size_t)(g + NB + 0) * F_TOT);
            xn1 = __ldg(xp + (size_t)(g + NB + 1) * F_TOT);
            xn2 = __ldg(xp + (size_t)(g + NB + 2) * F_TOT);
            xn3 = __ldg(xp + (size_t)(g + NB + 3) * F_TOT);
        }

        const __half2 x01 = __floats2half2_rn(xc0, xc1);
        const __half2 x23 = __floats2half2_rn(xc2, xc3);

        float a0 = 0.f, a1 = 0.f, a2 = 0.f, a3 = 0.f;
#pragma unroll
        for (int h = 0; h < H_TOT; h++) {
            __half2 p01 = __hfma2(x01, w1h[h], b1h[h]);
            __half2 p23 = __hfma2(x23, w1h[h], b1h[h]);
            __half2 t01 = tanh2_fast(p01);
            __half2 t23 = tanh2_fast(p23);
            float2 f01 = __half22float2(t01);
            float2 f23 = __half22float2(t23);
            a0 = fmaf(f01.x, w2r[h], a0);
            a1 = fmaf(f01.y, w2r[h], a1);
            a2 = fmaf(f23.x, w2r[h], a2);
            a3 = fmaf(f23.y, w2r[h], a3);
        }

        // folded 4-accumulator warp reduction (11 SHFL)
        a0 += __shfl_xor_sync(0xFFFFFFFFu, a0, 16);
        a1 += __shfl_xor_sync(0xFFFFFFFFu, a1, 16);
        a2 += __shfl_xor_sync(0xFFFFFFFFu, a2, 16);
        a3 += __shfl_xor_sync(0xFFFFFFFFu, a3, 16);
        a0 += __shfl_xor_sync(0xFFFFFFFFu, a0, 8);
        a1 += __shfl_xor_sync(0xFFFFFFFFu, a1, 8);
        a2 += __shfl_xor_sync(0xFFFFFFFFu, a2, 8);
        a3 += __shfl_xor_sync(0xFFFFFFFFu, a3, 8);
        int q = (lane >> 3) & 3;                 // quarter selects its accumulator
        float c = (q == 0) ? a0 : (q == 1) ? a1 : (q == 2) ? a2 : a3;
        c += __shfl_xor_sync(0xFFFFFFFFu, c, 4);
        c += __shfl_xor_sync(0xFFFFFFFFu, c, 2);
        c += __shfl_xor_sync(0xFFFFFFFFu, c, 1);
        if ((lane & 7) == 0)
            part[(g + q) * 17 + warp] = c;

        xc0 = xn0; xc1 = xn1; xc2 = xn2; xc3 = xn3;
    }
    __syncthreads();

    if (tid < CHUNK) {
        float s = s_base;
#pragma unroll
        for (int w = 0; w < NWARP; w++) s += part[tid * 17 + w];
        y[bchunk + tid] = s;
    }
}

// ---------------------------------------------------------------------------
// kernel_launch: inputs in setup_inputs order:
//   0:x (B,F)  1:W1 (F,H)  2:b1 (F,H)  3:W2 (F,H)  4:b2 (F)  5:theta (F)  6:bias (1)
// output: y_pred (B) then nn_theta (F), fp32.
// ---------------------------------------------------------------------------
extern "C" void kernel_launch(void* const* d_in, const int* in_sizes, int n_in,
                              void* d_out, int out_size) {
    const float* x     = (const float*)d_in[0];
    const float* W1    = (const float*)d_in[1];
    const float* b1    = (const float*)d_in[2];
    const float* W2    = (const float*)d_in[3];
    const float* b2    = (const float*)d_in[4];
    const float* theta = (const float*)d_in[5];
    const float* bias  = (const float*)d_in[6];
    float* out = (float*)d_out;

    neural_unilasso_kernel<<<B_TOT / CHUNK, THREADS>>>(
        x, W1, b1, W2, b2, theta, bias, out, out + B_TOT);
}